// round 1
// baseline (speedup 1.0000x reference)
#include <cuda_runtime.h>

#define B_SZ   65536
#define IN_SZ  512
#define HID_SZ 512
#define FAN    1024
#define NZ     32          // NGATES * NQ
#define THREADS 512
#define NBLK   (B_SZ / THREADS)   // 128

typedef unsigned long long u64;

// Pre-transposed weights (filled by prep_kernel each launch; deterministic).
__device__ float g_W1t[FAN * NZ];          // [k][gq]     gq = g*8+q
__device__ float g_W2t[4 * 8 * HID_SZ];    // [g][q][h]

__device__ __forceinline__ u64 pk2(float a, float b) {
    u64 r; asm("mov.b64 %0, {%1,%2};" : "=l"(r) : "f"(a), "f"(b)); return r;
}
__device__ __forceinline__ void upk2(u64 v, float& a, float& b) {
    asm("mov.b64 {%0,%1}, %2;" : "=f"(a), "=f"(b) : "l"(v));
}
// packed dual-FMA on Blackwell fp32 pipe: d = a*b + d (two lanes)
__device__ __forceinline__ void ffma2(u64& d, u64 a, u64 b) {
    asm("fma.rn.f32x2 %0, %1, %2, %0;" : "+l"(d) : "l"(a), "l"(b));
}
__device__ __forceinline__ float sigm(float xv) {
    return __fdividef(1.0f, 1.0f + __expf(-xv));
}
__device__ __forceinline__ float tanh_acc(float xv) {
    return 2.0f * sigm(2.0f * xv) - 1.0f;
}

__global__ void prep_kernel(const float* __restrict__ W1, const float* __restrict__ W2) {
    int t = blockIdx.x * blockDim.x + threadIdx.x;
    if (t < FAN * NZ) {
        // W1 is [4][8][1024] -> W1t[k][gq]
        int k = t >> 5, gq = t & 31;
        g_W1t[t] = W1[gq * FAN + k];
    } else {
        int t2 = t - FAN * NZ;
        if (t2 < 4 * 8 * HID_SZ) {
            // W2 is [4][512][8] -> W2t[g][q][h]
            int g = t2 >> 12, rem = t2 & 4095, q = rem >> 9, hh = rem & 511;
            g_W2t[t2] = W2[g * 4096 + hh * 8 + q];
        }
    }
}

__global__ __launch_bounds__(THREADS, 1)
void lstm_kernel(const float* __restrict__ x, const float* __restrict__ h,
                 const float* __restrict__ c, const float* __restrict__ b1,
                 const float* __restrict__ b2, float* __restrict__ out) {
    extern __shared__ float smem[];
    float* W1s = smem;               // 32768 floats  (128 KB)  [k][32]
    float* W2s = smem + 32768;       // 16384 floats  ( 64 KB)  [g][q][512]
    float* b2s = smem + 49152;       //  2048 floats  (  8 KB)  [g][512]
    float* b1s = smem + 51200;       //    32 floats

    const int tid = threadIdx.x;
    {   // cooperative smem fill (coalesced, conflict-free)
        float4* d1 = (float4*)W1s; const float4* s1 = (const float4*)g_W1t;
        for (int i = tid; i < 8192; i += THREADS) d1[i] = s1[i];
        float4* d2 = (float4*)W2s; const float4* s2 = (const float4*)g_W2t;
        for (int i = tid; i < 4096; i += THREADS) d2[i] = s2[i];
        float4* d3 = (float4*)b2s; const float4* s3 = (const float4*)b2;
        for (int i = tid; i < 512; i += THREADS) d3[i] = s3[i];
        if (tid < 32) b1s[tid] = b1[tid];
    }
    __syncthreads();

    const int row = blockIdx.x * THREADS + tid;
    const float* xr = x + (size_t)row * IN_SZ;
    const float* hr = h + (size_t)row * HID_SZ;

    // ---------------- GEMM1: z_pre[32] = combined[1024] . W1t ----------------
    // acc[p] holds fp32x2 pair (gq=2p, gq=2p+1)
    u64 acc[16];
    #pragma unroll
    for (int p = 0; p < 16; p++) acc[p] = 0ULL;

    float4 v = *(const float4*)xr;
    #pragma unroll 1
    for (int k0 = 0; k0 < FAN; k0 += 4) {
        const int kn = k0 + 4;
        float4 vn = v;
        if (kn < FAN)
            vn = *(const float4*)((kn < IN_SZ) ? (xr + kn) : (hr + (kn - IN_SZ)));
        float cv[4] = {v.x, v.y, v.z, v.w};
        #pragma unroll
        for (int kk = 0; kk < 4; kk++) {
            u64 a2 = pk2(cv[kk], cv[kk]);
            const ulonglong2* wr = (const ulonglong2*)(W1s + (k0 + kk) * NZ);
            #pragma unroll
            for (int p = 0; p < 8; p++) {
                ulonglong2 w = wr[p];          // LDS.128: 4 W1 values (2 pairs), broadcast
                ffma2(acc[2*p],     a2, w.x);
                ffma2(acc[2*p + 1], a2, w.y);
            }
        }
        v = vn;
    }

    // z = tanh(z_pre + b1); duplicate-pack each z into both f32x2 lanes
    u64 z2[32];
    #pragma unroll
    for (int p = 0; p < 16; p++) {
        float a, b; upk2(acc[p], a, b);
        a = tanh_acc(a + b1s[2*p]);
        b = tanh_acc(b + b1s[2*p + 1]);
        z2[2*p]     = pk2(a, a);
        z2[2*p + 1] = pk2(b, b);
    }

    // ---------------- GEMM2 + gating epilogue, 4 h-outputs per iteration ----------------
    const float* cr  = c   + (size_t)row * HID_SZ;
    float* hnr = out + (size_t)row * HID_SZ;
    float* cnr = out + (size_t)B_SZ * HID_SZ + (size_t)row * HID_SZ;

    #pragma unroll 1
    for (int h0 = 0; h0 < HID_SZ; h0 += 4) {
        float pre[4][4];
        #pragma unroll
        for (int g = 0; g < 4; g++) {
            ulonglong2 bb = *(const ulonglong2*)(b2s + g * HID_SZ + h0);
            u64 a0 = bb.x, a1 = bb.y;        // pairs (h0,h0+1) and (h0+2,h0+3)
            const float* wg = W2s + g * (8 * HID_SZ) + h0;
            #pragma unroll
            for (int q = 0; q < 8; q++) {
                ulonglong2 w = *(const ulonglong2*)(wg + q * HID_SZ);
                ffma2(a0, z2[g*8 + q], w.x);
                ffma2(a1, z2[g*8 + q], w.y);
            }
            upk2(a0, pre[g][0], pre[g][1]);
            upk2(a1, pre[g][2], pre[g][3]);
        }
        float4 cvv = *(const float4*)(cr + h0);
        float ca[4] = {cvv.x, cvv.y, cvv.z, cvv.w};
        float hn[4], cn[4];
        #pragma unroll
        for (int j = 0; j < 4; j++) {
            float ig = sigm(pre[0][j]);
            float fg = sigm(pre[1][j]);
            float og = sigm(pre[2][j]);
            float gg = sigm(pre[3][j]);
            float cj = fg * ca[j] + ig * gg;
            cn[j] = cj;
            hn[j] = og * tanh_acc(cj);
        }
        *(float4*)(hnr + h0) = make_float4(hn[0], hn[1], hn[2], hn[3]);
        *(float4*)(cnr + h0) = make_float4(cn[0], cn[1], cn[2], cn[3]);
    }
}

extern "C" void kernel_launch(void* const* d_in, const int* in_sizes, int n_in,
                              void* d_out, int out_size) {
    const float* x  = (const float*)d_in[0];
    const float* h  = (const float*)d_in[1];
    const float* c  = (const float*)d_in[2];
    const float* W1 = (const float*)d_in[3];
    const float* b1 = (const float*)d_in[4];
    const float* W2 = (const float*)d_in[5];
    const float* b2 = (const float*)d_in[6];
    float* out = (float*)d_out;

    prep_kernel<<<192, 256>>>(W1, W2);   // 192*256 = 49152 = 32768 + 16384

    const size_t smem_bytes = (size_t)(32768 + 16384 + 2048 + 32) * sizeof(float); // 204,928 B
    cudaFuncSetAttribute(lstm_kernel, cudaFuncAttributeMaxDynamicSharedMemorySize,
                         (int)smem_bytes);
    lstm_kernel<<<NBLK, THREADS, smem_bytes>>>(x, h, c, b1, b2, out);
}

// round 2
// speedup vs baseline: 1.0028x; 1.0028x over previous
#include <cuda_runtime.h>

#define B_SZ   65536
#define IN_SZ  512
#define HID_SZ 512
#define FAN    1024
#define NZ     32          // NGATES * NQ
#define THREADS 512
#define NBLK   (B_SZ / THREADS)   // 128

typedef unsigned long long u64;

// Pre-transposed weights (filled by prep_kernel each launch; deterministic).
__device__ float g_W1t[FAN * NZ];          // [k][gq]     gq = g*8+q
__device__ float g_W2t[4 * 8 * HID_SZ];    // [g][q][h]

__device__ __forceinline__ u64 pk2(float a, float b) {
    u64 r; asm("mov.b64 %0, {%1,%2};" : "=l"(r) : "f"(a), "f"(b)); return r;
}
__device__ __forceinline__ void upk2(u64 v, float& a, float& b) {
    asm("mov.b64 {%0,%1}, %2;" : "=f"(a), "=f"(b) : "l"(v));
}
// packed dual-FMA on Blackwell fp32 pipe: d = a*b + d (two lanes)
__device__ __forceinline__ void ffma2(u64& d, u64 a, u64 b) {
    asm("fma.rn.f32x2 %0, %1, %2, %0;" : "+l"(d) : "l"(a), "l"(b));
}
__device__ __forceinline__ float sigm(float xv) {
    return __fdividef(1.0f, 1.0f + __expf(-xv));
}
__device__ __forceinline__ float tanh_acc(float xv) {
    return 2.0f * sigm(2.0f * xv) - 1.0f;
}

__global__ void prep_kernel(const float* __restrict__ W1, const float* __restrict__ W2) {
    int t = blockIdx.x * blockDim.x + threadIdx.x;
    if (t < FAN * NZ) {
        // W1 is [4][8][1024] -> W1t[k][gq]
        int k = t >> 5, gq = t & 31;
        g_W1t[t] = W1[gq * FAN + k];
    } else {
        int t2 = t - FAN * NZ;
        if (t2 < 4 * 8 * HID_SZ) {
            // W2 is [4][512][8] -> W2t[g][q][h]
            int g = t2 >> 12, rem = t2 & 4095, q = rem >> 9, hh = rem & 511;
            g_W2t[t2] = W2[g * 4096 + hh * 8 + q];
        }
    }
}

__global__ __launch_bounds__(THREADS, 1)
void lstm_kernel(const float* __restrict__ x, const float* __restrict__ h,
                 const float* __restrict__ c, const float* __restrict__ b1,
                 const float* __restrict__ b2, float* __restrict__ out) {
    extern __shared__ float smem[];
    float* W1s = smem;               // 32768 floats  (128 KB)  [k][32]
    float* W2s = smem + 32768;       // 16384 floats  ( 64 KB)  [g][q][512]
    float* b2s = smem + 49152;       //  2048 floats  (  8 KB)  [g][512]
    float* b1s = smem + 51200;       //    32 floats

    const int tid = threadIdx.x;
    {   // cooperative smem fill (coalesced, conflict-free)
        float4* d1 = (float4*)W1s; const float4* s1 = (const float4*)g_W1t;
        for (int i = tid; i < 8192; i += THREADS) d1[i] = s1[i];
        float4* d2 = (float4*)W2s; const float4* s2 = (const float4*)g_W2t;
        for (int i = tid; i < 4096; i += THREADS) d2[i] = s2[i];
        float4* d3 = (float4*)b2s; const float4* s3 = (const float4*)b2;
        for (int i = tid; i < 512; i += THREADS) d3[i] = s3[i];
        if (tid < 32) b1s[tid] = b1[tid];
    }
    __syncthreads();

    const int row = blockIdx.x * THREADS + tid;
    const float* xr = x + (size_t)row * IN_SZ;
    const float* hr = h + (size_t)row * HID_SZ;

    // ---------------- GEMM1: z_pre[32] = combined[1024] . W1t ----------------
    // acc[p] holds fp32x2 pair (gq=2p, gq=2p+1)
    u64 acc[16];
    #pragma unroll
    for (int p = 0; p < 16; p++) acc[p] = 0ULL;

    float4 v = *(const float4*)xr;
    #pragma unroll 1
    for (int k0 = 0; k0 < FAN; k0 += 4) {
        const int kn = k0 + 4;
        float4 vn = v;
        if (kn < FAN)
            vn = *(const float4*)((kn < IN_SZ) ? (xr + kn) : (hr + (kn - IN_SZ)));
        float cv[4] = {v.x, v.y, v.z, v.w};
        #pragma unroll
        for (int kk = 0; kk < 4; kk++) {
            u64 a2 = pk2(cv[kk], cv[kk]);
            const ulonglong2* wr = (const ulonglong2*)(W1s + (k0 + kk) * NZ);
            #pragma unroll
            for (int p = 0; p < 8; p++) {
                ulonglong2 w = wr[p];          // LDS.128: 4 W1 values (2 pairs), broadcast
                ffma2(acc[2*p],     a2, w.x);
                ffma2(acc[2*p + 1], a2, w.y);
            }
        }
        v = vn;
    }

    // z = tanh(z_pre + b1); duplicate-pack each z into both f32x2 lanes
    u64 z2[32];
    #pragma unroll
    for (int p = 0; p < 16; p++) {
        float a, b; upk2(acc[p], a, b);
        a = tanh_acc(a + b1s[2*p]);
        b = tanh_acc(b + b1s[2*p + 1]);
        z2[2*p]     = pk2(a, a);
        z2[2*p + 1] = pk2(b, b);
    }

    // ---------------- GEMM2 + gating epilogue, 4 h-outputs per iteration ----------------
    const float* cr  = c   + (size_t)row * HID_SZ;
    float* hnr = out + (size_t)row * HID_SZ;
    float* cnr = out + (size_t)B_SZ * HID_SZ + (size_t)row * HID_SZ;

    #pragma unroll 1
    for (int h0 = 0; h0 < HID_SZ; h0 += 4) {
        float pre[4][4];
        #pragma unroll
        for (int g = 0; g < 4; g++) {
            ulonglong2 bb = *(const ulonglong2*)(b2s + g * HID_SZ + h0);
            u64 a0 = bb.x, a1 = bb.y;        // pairs (h0,h0+1) and (h0+2,h0+3)
            const float* wg = W2s + g * (8 * HID_SZ) + h0;
            #pragma unroll
            for (int q = 0; q < 8; q++) {
                ulonglong2 w = *(const ulonglong2*)(wg + q * HID_SZ);
                ffma2(a0, z2[g*8 + q], w.x);
                ffma2(a1, z2[g*8 + q], w.y);
            }
            upk2(a0, pre[g][0], pre[g][1]);
            upk2(a1, pre[g][2], pre[g][3]);
        }
        float4 cvv = *(const float4*)(cr + h0);
        float ca[4] = {cvv.x, cvv.y, cvv.z, cvv.w};
        float hn[4], cn[4];
        #pragma unroll
        for (int j = 0; j < 4; j++) {
            float ig = sigm(pre[0][j]);
            float fg = sigm(pre[1][j]);
            float og = sigm(pre[2][j]);
            float gg = sigm(pre[3][j]);
            float cj = fg * ca[j] + ig * gg;
            cn[j] = cj;
            hn[j] = og * tanh_acc(cj);
        }
        *(float4*)(hnr + h0) = make_float4(hn[0], hn[1], hn[2], hn[3]);
        *(float4*)(cnr + h0) = make_float4(cn[0], cn[1], cn[2], cn[3]);
    }
}

extern "C" void kernel_launch(void* const* d_in, const int* in_sizes, int n_in,
                              void* d_out, int out_size) {
    const float* x  = (const float*)d_in[0];
    const float* h  = (const float*)d_in[1];
    const float* c  = (const float*)d_in[2];
    const float* W1 = (const float*)d_in[3];
    const float* b1 = (const float*)d_in[4];
    const float* W2 = (const float*)d_in[5];
    const float* b2 = (const float*)d_in[6];
    float* out = (float*)d_out;

    prep_kernel<<<192, 256>>>(W1, W2);   // 192*256 = 49152 = 32768 + 16384

    const size_t smem_bytes = (size_t)(32768 + 16384 + 2048 + 32) * sizeof(float); // 204,928 B
    cudaFuncSetAttribute(lstm_kernel, cudaFuncAttributeMaxDynamicSharedMemorySize,
                         (int)smem_bytes);
    lstm_kernel<<<NBLK, THREADS, smem_bytes>>>(x, h, c, b1, b2, out);
}